// round 11
// baseline (speedup 1.0000x reference)
#include <cuda_runtime.h>
#include <cuda_fp16.h>
#include <cstdint>

#define NN 50000
#define EE 800000
#define HH 64
#define CC 10
#define CAP 96   // bucket capacity per dst row (max in-degree ~42; 20+ sigma margin)

// Scratch (allocation-free: __device__ globals; zero-init at load, re-zeroed
// by the tail of k_final2 each replay)
__device__ int g_degi[NN];              // out-degree by src
__device__ int g_cnt[NN];               // in-degree by dst (bucket fill level)
__device__ int g_srcs[NN * CAP];        // bucketed src indices: row d at d*CAP
__device__ __align__(16) __half g_h16[NN * HH];   // fp16 h
__device__ __align__(16) __half g_lap16[NN * HH]; // fp16 lap

// ---------------------------------------------------------------------------
__device__ __forceinline__ int detect_stride(const int* __restrict__ p, int* s_st) {
    if (threadIdx.x < 32) {
        int bad = (p[2 * threadIdx.x + 1] != 0);
        unsigned b = __ballot_sync(0xffffffffu, bad);
        if (threadIdx.x == 0) *s_st = b ? 1 : 2;
    }
    __syncthreads();
    return *s_st;
}

// ---------------------------------------------------------------------------
// mma.sync helpers
// ---------------------------------------------------------------------------
__device__ __forceinline__ void ldsm_x4(uint32_t& r0, uint32_t& r1, uint32_t& r2,
                                        uint32_t& r3, uint32_t addr) {
    asm volatile("ldmatrix.sync.aligned.m8n8.x4.shared.b16 {%0,%1,%2,%3}, [%4];"
                 : "=r"(r0), "=r"(r1), "=r"(r2), "=r"(r3) : "r"(addr));
}
__device__ __forceinline__ void ldsm_x4_t(uint32_t& r0, uint32_t& r1, uint32_t& r2,
                                          uint32_t& r3, uint32_t addr) {
    asm volatile("ldmatrix.sync.aligned.m8n8.x4.trans.shared.b16 {%0,%1,%2,%3}, [%4];"
                 : "=r"(r0), "=r"(r1), "=r"(r2), "=r"(r3) : "r"(addr));
}
__device__ __forceinline__ void mma16816(float* c, uint32_t a0, uint32_t a1,
                                         uint32_t a2, uint32_t a3,
                                         uint32_t b0, uint32_t b1) {
    asm volatile(
        "mma.sync.aligned.m16n8k16.row.col.f32.f16.f16.f32 "
        "{%0,%1,%2,%3}, {%4,%5,%6,%7}, {%8,%9}, {%0,%1,%2,%3};"
        : "+f"(c[0]), "+f"(c[1]), "+f"(c[2]), "+f"(c[3])
        : "r"(a0), "r"(a1), "r"(a2), "r"(a3), "r"(b0), "r"(b1));
}

// ---------------------------------------------------------------------------
// A0: fused hist + bucket fill (single pass over edges). 8 edges/thread ILP.
// ---------------------------------------------------------------------------
__global__ __launch_bounds__(512) void k_fill(const int* __restrict__ ei) {
    __shared__ int s_st;
    int st = detect_stride(ei, &s_st);
    int base = blockIdx.x * 4096 + threadIdx.x;
    int s[8], d[8], pos[8];
#pragma unroll
    for (int j = 0; j < 8; j++) {
        int e = base + j * 512;
        if (e < EE) {
            s[j] = __ldg(&ei[e * st]);
            d[j] = __ldg(&ei[(EE + e) * st]);
        } else { s[j] = -1; d[j] = 0; }
    }
#pragma unroll
    for (int j = 0; j < 8; j++)
        if (s[j] >= 0) pos[j] = atomicAdd(&g_cnt[d[j]], 1);
#pragma unroll
    for (int j = 0; j < 8; j++)
        if (s[j] >= 0) {
            if (pos[j] < CAP) g_srcs[d[j] * CAP + pos[j]] = s[j];
            atomicAdd(&g_degi[s[j]], 1);
        }
}

// ---------------------------------------------------------------------------
// B0 (concurrent stream): GEMM1  h16 = fp16(relu(x@W1+b1))
// ---------------------------------------------------------------------------
__global__ __launch_bounds__(512, 2) void k_gemm1(const float* __restrict__ x,
                                                  const float* __restrict__ W1,
                                                  const float* __restrict__ b1) {
    __shared__ __align__(16) float sm[12288];
    float* Ws = sm;          // [64][64]
    float* xs = sm + 4096;   // [128][64]
    int tid = threadIdx.x;
    int rowbase = blockIdx.x * 128;

    for (int i = tid; i < HH * HH; i += 512) Ws[i] = W1[i];
#pragma unroll
    for (int j = 0; j < 4; j++) {
        int idx = j * 512 + tid;
        int r = idx >> 4;
        int kq = (idx & 15) << 2;
        int grow = rowbase + r;
        float4 v = make_float4(0.f, 0.f, 0.f, 0.f);
        if (grow < NN) v = *(const float4*)&x[grow * HH + kq];
        *(float4*)&xs[r * HH + kq] = v;
    }
    __syncthreads();

    int tx = tid & 15, ty = tid >> 4;
    int c0 = tx * 4, r0 = ty * 4;
    float4 bv = *(const float4*)&b1[c0];
    float acc[4][4];
#pragma unroll
    for (int r = 0; r < 4; r++) {
        acc[r][0] = bv.x; acc[r][1] = bv.y; acc[r][2] = bv.z; acc[r][3] = bv.w;
    }

#pragma unroll 8
    for (int k = 0; k < HH; k += 2) {
        float4 wa = *(const float4*)&Ws[k * HH + c0];
        float4 wb = *(const float4*)&Ws[(k + 1) * HH + c0];
#pragma unroll
        for (int r = 0; r < 4; r++) {
            float2 xv = *(const float2*)&xs[(r0 + r) * HH + k];
            acc[r][0] = fmaf(xv.x, wa.x, acc[r][0]);
            acc[r][1] = fmaf(xv.x, wa.y, acc[r][1]);
            acc[r][2] = fmaf(xv.x, wa.z, acc[r][2]);
            acc[r][3] = fmaf(xv.x, wa.w, acc[r][3]);
            acc[r][0] = fmaf(xv.y, wb.x, acc[r][0]);
            acc[r][1] = fmaf(xv.y, wb.y, acc[r][1]);
            acc[r][2] = fmaf(xv.y, wb.z, acc[r][2]);
            acc[r][3] = fmaf(xv.y, wb.w, acc[r][3]);
        }
    }

#pragma unroll
    for (int r = 0; r < 4; r++) {
        int row = rowbase + r0 + r;
        if (row < NN) {
            __half2 p0 = __floats2half2_rn(fmaxf(acc[r][0], 0.f), fmaxf(acc[r][1], 0.f));
            __half2 p1 = __floats2half2_rn(fmaxf(acc[r][2], 0.f), fmaxf(acc[r][3], 0.f));
            uint2 pk;
            pk.x = *(unsigned*)&p0;
            pk.y = *(unsigned*)&p1;
            *(uint2*)&g_h16[row * HH + c0] = pk;
        }
    }
}

// ---------------------------------------------------------------------------
// A1 (after join): bucket gather -> lap16
// ---------------------------------------------------------------------------
__global__ __launch_bounds__(256) void k_gather() {
    int gt = blockIdx.x * 256 + threadIdx.x;
    int row = gt >> 3;
    int l = gt & 7;
    if (row >= NN) return;
    unsigned gmask = 0xffu << (threadIdx.x & 24);  // own 8-lane group

    int len = min(__ldg(&g_cnt[row]), CAP);
    int start = row * CAP;

    float a0 = 0.f, a1 = 0.f, a2 = 0.f, a3 = 0.f;
    float a4 = 0.f, a5 = 0.f, a6 = 0.f, a7 = 0.f;

    for (int base = 0; base < len; base += 8) {
        int j = base + l;
        int s = 0;
        float w = 0.f;
        if (j < len) {
            s = __ldg(&g_srcs[start + j]);
            int dg = __ldg(&g_degi[s]);
            w = (dg > 0) ? rsqrtf((float)dg) : 0.f;
        }
        int m = min(8, len - base);
#pragma unroll 4
        for (int jj = 0; jj < m; jj++) {
            int sj = __shfl_sync(gmask, s, jj, 8);
            float wj = __shfl_sync(gmask, w, jj, 8);
            uint4 u = __ldg((const uint4*)&g_h16[sj * HH + l * 8]);
            float2 f0 = __half22float2(*(__half2*)&u.x);
            float2 f1 = __half22float2(*(__half2*)&u.y);
            float2 f2 = __half22float2(*(__half2*)&u.z);
            float2 f3 = __half22float2(*(__half2*)&u.w);
            a0 = fmaf(wj, f0.x, a0); a1 = fmaf(wj, f0.y, a1);
            a2 = fmaf(wj, f1.x, a2); a3 = fmaf(wj, f1.y, a3);
            a4 = fmaf(wj, f2.x, a4); a5 = fmaf(wj, f2.y, a5);
            a6 = fmaf(wj, f3.x, a6); a7 = fmaf(wj, f3.y, a7);
        }
    }
    int dgr = __ldg(&g_degi[row]);
    float sc = (dgr > 0) ? -rsqrtf((float)dgr) : 0.f;
    __half2 o0 = __floats2half2_rn(a0 * sc, a1 * sc);
    __half2 o1 = __floats2half2_rn(a2 * sc, a3 * sc);
    __half2 o2 = __floats2half2_rn(a4 * sc, a5 * sc);
    __half2 o3 = __floats2half2_rn(a6 * sc, a7 * sc);
    uint4 ov;
    ov.x = *(unsigned*)&o0; ov.y = *(unsigned*)&o1;
    ov.z = *(unsigned*)&o2; ov.w = *(unsigned*)&o3;
    *(uint4*)&g_lap16[row * HH + l * 8] = ov;
}

// ---------------------------------------------------------------------------
// A2: tensor-core dual GEMM + register/shuffle epilogue.
//   acc = h16 @ W20 + lap16 @ W21 + b2  via mma.m16n8k16 (fp32 accum)
//   Then, entirely in registers: s = relu(acc)+h16; partial logits over the
//   thread's 16 k-columns; quad shfl_xor reduce; quad leader does
//   log_softmax and writes 2 rows. ONE __syncthreads total.
// ---------------------------------------------------------------------------
#define SW 72
#define OFF_H 0
#define OFF_L 18432
#define OFF_W20 36864
#define OFF_W21 46080
#define OFF_WL 55296            // Wl fp32 [64][10] = 2560 B
#define SMEM_F2 57856

__global__ __launch_bounds__(256) void k_final2(const float* __restrict__ W20,
                                                const float* __restrict__ W21,
                                                const float* __restrict__ b2,
                                                const float* __restrict__ Wl,
                                                const float* __restrict__ bl,
                                                float* __restrict__ out) {
    extern __shared__ char dsm[];
    __half* Hs = (__half*)(dsm + OFF_H);
    __half* Ls = (__half*)(dsm + OFF_L);
    __half* W20s = (__half*)(dsm + OFF_W20);
    __half* W21s = (__half*)(dsm + OFF_W21);
    float* Wlf = (float*)(dsm + OFF_WL);

    int tid = threadIdx.x;
    int rowbase = blockIdx.x * 128;

    // Load weights (f32 -> fp16 smem, stride SW) + Wl (f32)
    for (int i = tid; i < HH * HH; i += 256) {
        int k = i >> 6, n = i & 63;
        W20s[k * SW + n] = __float2half(W20[i]);
        W21s[k * SW + n] = __float2half(W21[i]);
    }
    for (int i = tid; i < HH * CC; i += 256) Wlf[i] = __ldg(&Wl[i]);
    // Load h16/lap16 tiles (uint4 = 8 halves)
#pragma unroll
    for (int j = 0; j < 8; j++) {
        int idx = j * 256 + tid;           // 0..2047
        int half_sel = idx >> 10;          // 0: h, 1: lap
        int r = (idx >> 3) & 127;
        int c8 = (idx & 7) * 8;
        int grow = rowbase + r;
        uint4 v = make_uint4(0u, 0u, 0u, 0u);
        if (grow < NN) {
            const uint4* src = half_sel ? (const uint4*)&g_lap16[grow * HH + c8]
                                        : (const uint4*)&g_h16[grow * HH + c8];
            v = __ldg(src);
        }
        __half* dst = half_sel ? &Ls[r * SW + c8] : &Hs[r * SW + c8];
        *(uint4*)dst = v;
    }
    __syncthreads();

    int warp = tid >> 5, lane = tid & 31;
    int R0 = warp * 16;
    uint32_t sb = (uint32_t)__cvta_generic_to_shared(dsm);

    float acc[8][4];
    int cq = 2 * (lane & 3);
    int rr = lane >> 2;
#pragma unroll
    for (int q = 0; q < 8; q++) {
        float bb0 = __ldg(&b2[q * 8 + cq]);
        float bb1 = __ldg(&b2[q * 8 + cq + 1]);
        acc[q][0] = bb0; acc[q][1] = bb1; acc[q][2] = bb0; acc[q][3] = bb1;
    }

    int ar = R0 + (lane & 15);
    int ac = (lane >> 4) << 3;
    int br = ((lane >> 3) & 1) * 8 + (lane & 7);
    int bc = (lane >> 4) << 3;

#pragma unroll
    for (int ki = 0; ki < 4; ki++) {
        int k0 = ki * 16;
        uint32_t ha0, ha1, ha2, ha3, la0, la1, la2, la3;
        ldsm_x4(ha0, ha1, ha2, ha3, sb + OFF_H + (ar * SW + k0 + ac) * 2);
        ldsm_x4(la0, la1, la2, la3, sb + OFF_L + (ar * SW + k0 + ac) * 2);
#pragma unroll
        for (int p = 0; p < 4; p++) {
            int n0 = p * 16;
            uint32_t w0, w1, w2, w3;
            ldsm_x4_t(w0, w1, w2, w3, sb + OFF_W20 + ((k0 + br) * SW + n0 + bc) * 2);
            mma16816(acc[2 * p],     ha0, ha1, ha2, ha3, w0, w1);
            mma16816(acc[2 * p + 1], ha0, ha1, ha2, ha3, w2, w3);
            uint32_t v0, v1, v2, v3;
            ldsm_x4_t(v0, v1, v2, v3, sb + OFF_W21 + ((k0 + br) * SW + n0 + bc) * 2);
            mma16816(acc[2 * p],     la0, la1, la2, la3, v0, v1);
            mma16816(acc[2 * p + 1], la0, la1, la2, la3, v2, v3);
        }
    }

    // Register/shuffle epilogue: two row-halves per thread.
    // Row half hsel=0: row R0+rr (acc[q][0..1]); hsel=1: row R0+rr+8 (acc[q][2..3]).
#pragma unroll
    for (int hsel = 0; hsel < 2; hsel++) {
        int rl = R0 + rr + hsel * 8;
        float pl[CC];
#pragma unroll
        for (int c = 0; c < CC; c++) pl[c] = 0.f;
#pragma unroll
        for (int q = 0; q < 8; q++) {
            int k0 = q * 8 + cq;
            float2 hv = __half22float2(*(__half2*)&Hs[rl * SW + k0]);
            float s0 = fmaxf(acc[q][2 * hsel], 0.f) + hv.x;
            float s1 = fmaxf(acc[q][2 * hsel + 1], 0.f) + hv.y;
            const float* w0 = &Wlf[k0 * CC];
            const float* w1 = &Wlf[(k0 + 1) * CC];
#pragma unroll
            for (int c = 0; c < CC; c++)
                pl[c] = fmaf(s0, w0[c], fmaf(s1, w1[c], pl[c]));
        }
#pragma unroll
        for (int c = 0; c < CC; c++) {
            pl[c] += __shfl_xor_sync(0xffffffffu, pl[c], 1);
            pl[c] += __shfl_xor_sync(0xffffffffu, pl[c], 2);
        }
        if ((lane & 3) == 0) {
            int row = rowbase + rl;
            if (row < NN) {
                float m = -1e30f;
#pragma unroll
                for (int c = 0; c < CC; c++) {
                    pl[c] += __ldg(&bl[c]);
                    m = fmaxf(m, pl[c]);
                }
                float sum = 0.f;
#pragma unroll
                for (int c = 0; c < CC; c++) sum += expf(pl[c] - m);
                float lse = logf(sum);
#pragma unroll
                for (int c = 0; c < CC; c++) out[row * CC + c] = pl[c] - m - lse;
            }
        }
    }

    // Tail: reset cnt/degi for next replay
    if (tid < 128) {
        int row = rowbase + tid;
        if (row < NN) g_cnt[row] = 0;
    }
    for (int i = blockIdx.x * 256 + tid; i < NN; i += gridDim.x * 256) g_degi[i] = 0;
}

// ---------------------------------------------------------------------------
extern "C" void kernel_launch(void* const* d_in, const int* in_sizes, int n_in,
                              void* d_out, int out_size) {
    const float* x   = (const float*)d_in[0];
    const int*   ei  = (const int*)d_in[1];
    const float* W1  = (const float*)d_in[2];
    const float* b1  = (const float*)d_in[3];
    const float* W20 = (const float*)d_in[4];
    const float* W21 = (const float*)d_in[5];
    const float* b2  = (const float*)d_in[6];
    const float* Wl  = (const float*)d_in[7];
    const float* bl  = (const float*)d_in[8];
    float* out = (float*)d_out;

    static cudaStream_t sB = 0;
    static cudaEvent_t e0 = 0, e1 = 0;
    static int init_done = 0;
    if (!init_done) {
        cudaFuncSetAttribute(k_final2, cudaFuncAttributeMaxDynamicSharedMemorySize, SMEM_F2);
        cudaStreamCreateWithFlags(&sB, cudaStreamNonBlocking);
        cudaEventCreateWithFlags(&e0, cudaEventDisableTiming);
        cudaEventCreateWithFlags(&e1, cudaEventDisableTiming);
        init_done = 1;
    }

    const int GB = (NN + 127) / 128;     // 391
    const int EB = (EE + 4095) / 4096;   // 196

    // Fork stream B for the graph-independent GEMM1
    cudaEventRecord(e0, 0);
    cudaStreamWaitEvent(sB, e0, 0);
    k_gemm1<<<GB, 512, 0, sB>>>(x, W1, b1);
    cudaEventRecord(e1, sB);

    // Stream A: fused hist+fill (single edge pass)
    k_fill<<<EB, 512>>>(ei);

    // Join: gather needs h16 (B) + buckets (A)
    cudaStreamWaitEvent(0, e1, 0);
    k_gather<<<(NN * 8 + 255) / 256, 256>>>();
    k_final2<<<GB, 256, SMEM_F2>>>(W20, W21, b2, Wl, bl, out);
}

// round 12
// speedup vs baseline: 1.0297x; 1.0297x over previous
#include <cuda_runtime.h>
#include <cuda_fp16.h>
#include <cstdint>

#define NN 50000
#define EE 800000
#define HH 64
#define CC 10
#define CAP 96   // bucket capacity per dst row (max in-degree ~42; 20+ sigma margin)

// Scratch (allocation-free: __device__ globals; zero-init at load, re-zeroed
// by the tail of k_final2 each replay)
__device__ int g_degi[NN];              // out-degree by src
__device__ int g_cnt[NN];               // in-degree by dst (bucket fill level)
__device__ int g_srcs[NN * CAP];        // bucketed src indices: row d at d*CAP
__device__ __align__(16) __half g_h16[NN * HH];   // fp16 h
__device__ __align__(16) __half g_lap16[NN * HH]; // fp16 lap

// ---------------------------------------------------------------------------
__device__ __forceinline__ int detect_stride(const int* __restrict__ p, int* s_st) {
    if (threadIdx.x < 32) {
        int bad = (p[2 * threadIdx.x + 1] != 0);
        unsigned b = __ballot_sync(0xffffffffu, bad);
        if (threadIdx.x == 0) *s_st = b ? 1 : 2;
    }
    __syncthreads();
    return *s_st;
}

// ---------------------------------------------------------------------------
// mma.sync helpers
// ---------------------------------------------------------------------------
__device__ __forceinline__ void ldsm_x4(uint32_t& r0, uint32_t& r1, uint32_t& r2,
                                        uint32_t& r3, uint32_t addr) {
    asm volatile("ldmatrix.sync.aligned.m8n8.x4.shared.b16 {%0,%1,%2,%3}, [%4];"
                 : "=r"(r0), "=r"(r1), "=r"(r2), "=r"(r3) : "r"(addr));
}
__device__ __forceinline__ void ldsm_x4_t(uint32_t& r0, uint32_t& r1, uint32_t& r2,
                                          uint32_t& r3, uint32_t addr) {
    asm volatile("ldmatrix.sync.aligned.m8n8.x4.trans.shared.b16 {%0,%1,%2,%3}, [%4];"
                 : "=r"(r0), "=r"(r1), "=r"(r2), "=r"(r3) : "r"(addr));
}
__device__ __forceinline__ void mma16816(float* c, uint32_t a0, uint32_t a1,
                                         uint32_t a2, uint32_t a3,
                                         uint32_t b0, uint32_t b1) {
    asm volatile(
        "mma.sync.aligned.m16n8k16.row.col.f32.f16.f16.f32 "
        "{%0,%1,%2,%3}, {%4,%5,%6,%7}, {%8,%9}, {%0,%1,%2,%3};"
        : "+f"(c[0]), "+f"(c[1]), "+f"(c[2]), "+f"(c[3])
        : "r"(a0), "r"(a1), "r"(a2), "r"(a3), "r"(b0), "r"(b1));
}

// ---------------------------------------------------------------------------
// A0: fused hist + bucket fill (single pass over edges). 8 edges/thread ILP.
// ---------------------------------------------------------------------------
__global__ __launch_bounds__(512) void k_fill(const int* __restrict__ ei) {
    __shared__ int s_st;
    int st = detect_stride(ei, &s_st);
    int base = blockIdx.x * 4096 + threadIdx.x;
    int s[8], d[8], pos[8];
#pragma unroll
    for (int j = 0; j < 8; j++) {
        int e = base + j * 512;
        if (e < EE) {
            s[j] = __ldg(&ei[e * st]);
            d[j] = __ldg(&ei[(EE + e) * st]);
        } else { s[j] = -1; d[j] = 0; }
    }
#pragma unroll
    for (int j = 0; j < 8; j++)
        if (s[j] >= 0) pos[j] = atomicAdd(&g_cnt[d[j]], 1);
#pragma unroll
    for (int j = 0; j < 8; j++)
        if (s[j] >= 0) {
            if (pos[j] < CAP) g_srcs[d[j] * CAP + pos[j]] = s[j];
            atomicAdd(&g_degi[s[j]], 1);
        }
}

// ---------------------------------------------------------------------------
// B0 (concurrent stream): GEMM1  h16 = fp16(relu(x@W1+b1))
// ---------------------------------------------------------------------------
__global__ __launch_bounds__(512, 2) void k_gemm1(const float* __restrict__ x,
                                                  const float* __restrict__ W1,
                                                  const float* __restrict__ b1) {
    __shared__ __align__(16) float sm[12288];
    float* Ws = sm;          // [64][64]
    float* xs = sm + 4096;   // [128][64]
    int tid = threadIdx.x;
    int rowbase = blockIdx.x * 128;

    for (int i = tid; i < HH * HH; i += 512) Ws[i] = W1[i];
#pragma unroll
    for (int j = 0; j < 4; j++) {
        int idx = j * 512 + tid;
        int r = idx >> 4;
        int kq = (idx & 15) << 2;
        int grow = rowbase + r;
        float4 v = make_float4(0.f, 0.f, 0.f, 0.f);
        if (grow < NN) v = *(const float4*)&x[grow * HH + kq];
        *(float4*)&xs[r * HH + kq] = v;
    }
    __syncthreads();

    int tx = tid & 15, ty = tid >> 4;
    int c0 = tx * 4, r0 = ty * 4;
    float4 bv = *(const float4*)&b1[c0];
    float acc[4][4];
#pragma unroll
    for (int r = 0; r < 4; r++) {
        acc[r][0] = bv.x; acc[r][1] = bv.y; acc[r][2] = bv.z; acc[r][3] = bv.w;
    }

#pragma unroll 8
    for (int k = 0; k < HH; k += 2) {
        float4 wa = *(const float4*)&Ws[k * HH + c0];
        float4 wb = *(const float4*)&Ws[(k + 1) * HH + c0];
#pragma unroll
        for (int r = 0; r < 4; r++) {
            float2 xv = *(const float2*)&xs[(r0 + r) * HH + k];
            acc[r][0] = fmaf(xv.x, wa.x, acc[r][0]);
            acc[r][1] = fmaf(xv.x, wa.y, acc[r][1]);
            acc[r][2] = fmaf(xv.x, wa.z, acc[r][2]);
            acc[r][3] = fmaf(xv.x, wa.w, acc[r][3]);
            acc[r][0] = fmaf(xv.y, wb.x, acc[r][0]);
            acc[r][1] = fmaf(xv.y, wb.y, acc[r][1]);
            acc[r][2] = fmaf(xv.y, wb.z, acc[r][2]);
            acc[r][3] = fmaf(xv.y, wb.w, acc[r][3]);
        }
    }

#pragma unroll
    for (int r = 0; r < 4; r++) {
        int row = rowbase + r0 + r;
        if (row < NN) {
            __half2 p0 = __floats2half2_rn(fmaxf(acc[r][0], 0.f), fmaxf(acc[r][1], 0.f));
            __half2 p1 = __floats2half2_rn(fmaxf(acc[r][2], 0.f), fmaxf(acc[r][3], 0.f));
            uint2 pk;
            pk.x = *(unsigned*)&p0;
            pk.y = *(unsigned*)&p1;
            *(uint2*)&g_h16[row * HH + c0] = pk;
        }
    }
}

// ---------------------------------------------------------------------------
// A1 (after join): bucket gather -> lap16
// ---------------------------------------------------------------------------
__global__ __launch_bounds__(256) void k_gather() {
    int gt = blockIdx.x * 256 + threadIdx.x;
    int row = gt >> 3;
    int l = gt & 7;
    if (row >= NN) return;
    unsigned gmask = 0xffu << (threadIdx.x & 24);  // own 8-lane group

    int len = min(__ldg(&g_cnt[row]), CAP);
    int start = row * CAP;

    float a0 = 0.f, a1 = 0.f, a2 = 0.f, a3 = 0.f;
    float a4 = 0.f, a5 = 0.f, a6 = 0.f, a7 = 0.f;

    for (int base = 0; base < len; base += 8) {
        int j = base + l;
        int s = 0;
        float w = 0.f;
        if (j < len) {
            s = __ldg(&g_srcs[start + j]);
            int dg = __ldg(&g_degi[s]);
            w = (dg > 0) ? rsqrtf((float)dg) : 0.f;
        }
        int m = min(8, len - base);
#pragma unroll 4
        for (int jj = 0; jj < m; jj++) {
            int sj = __shfl_sync(gmask, s, jj, 8);
            float wj = __shfl_sync(gmask, w, jj, 8);
            uint4 u = __ldg((const uint4*)&g_h16[sj * HH + l * 8]);
            float2 f0 = __half22float2(*(__half2*)&u.x);
            float2 f1 = __half22float2(*(__half2*)&u.y);
            float2 f2 = __half22float2(*(__half2*)&u.z);
            float2 f3 = __half22float2(*(__half2*)&u.w);
            a0 = fmaf(wj, f0.x, a0); a1 = fmaf(wj, f0.y, a1);
            a2 = fmaf(wj, f1.x, a2); a3 = fmaf(wj, f1.y, a3);
            a4 = fmaf(wj, f2.x, a4); a5 = fmaf(wj, f2.y, a5);
            a6 = fmaf(wj, f3.x, a6); a7 = fmaf(wj, f3.y, a7);
        }
    }
    int dgr = __ldg(&g_degi[row]);
    float sc = (dgr > 0) ? -rsqrtf((float)dgr) : 0.f;
    __half2 o0 = __floats2half2_rn(a0 * sc, a1 * sc);
    __half2 o1 = __floats2half2_rn(a2 * sc, a3 * sc);
    __half2 o2 = __floats2half2_rn(a4 * sc, a5 * sc);
    __half2 o3 = __floats2half2_rn(a6 * sc, a7 * sc);
    uint4 ov;
    ov.x = *(unsigned*)&o0; ov.y = *(unsigned*)&o1;
    ov.z = *(unsigned*)&o2; ov.w = *(unsigned*)&o3;
    *(uint4*)&g_lap16[row * HH + l * 8] = ov;
}

// ---------------------------------------------------------------------------
// A2: tensor-core dual GEMM + smem epilogue (R10 layout, Wl preloaded).
//   acc = h16 @ W20 + lap16 @ W21 + b2   via mma.m16n8k16 (fp32 accum)
//   s = relu(acc) + h16 -> Ls; logits pbuf = s@Wl + bl; log_softmax.
//   Dedicated smem regions for Wl (fp32) and pbuf -> only TWO syncs after
//   the tile-load sync (no mid-epilogue weight reload).
//   Tail: re-zero cnt/degi for the next replay.
// ---------------------------------------------------------------------------
#define SW 72
#define OFF_H 0
#define OFF_L 18432
#define OFF_W20 36864
#define OFF_W21 46080
#define OFF_WL 55296            // Wl fp32 [64][10] = 2560 B
#define OFF_PB 57856            // pbuf fp32 [128][10] = 5120 B
#define SMEM_F2 62976

__global__ __launch_bounds__(256) void k_final2(const float* __restrict__ W20,
                                                const float* __restrict__ W21,
                                                const float* __restrict__ b2,
                                                const float* __restrict__ Wl,
                                                const float* __restrict__ bl,
                                                float* __restrict__ out) {
    extern __shared__ char dsm[];
    __half* Hs = (__half*)(dsm + OFF_H);
    __half* Ls = (__half*)(dsm + OFF_L);
    __half* W20s = (__half*)(dsm + OFF_W20);
    __half* W21s = (__half*)(dsm + OFF_W21);
    float* Wlf = (float*)(dsm + OFF_WL);
    float* pb  = (float*)(dsm + OFF_PB);

    int tid = threadIdx.x;
    int rowbase = blockIdx.x * 128;

    // Load weights (f32 -> fp16 smem, stride SW) + Wl (f32, dedicated region)
    for (int i = tid; i < HH * HH; i += 256) {
        int k = i >> 6, n = i & 63;
        W20s[k * SW + n] = __float2half(W20[i]);
        W21s[k * SW + n] = __float2half(W21[i]);
    }
    for (int i = tid; i < HH * CC; i += 256) Wlf[i] = __ldg(&Wl[i]);
    // Load h16/lap16 tiles (uint4 = 8 halves)
#pragma unroll
    for (int j = 0; j < 8; j++) {
        int idx = j * 256 + tid;           // 0..2047
        int half_sel = idx >> 10;          // 0: h, 1: lap
        int r = (idx >> 3) & 127;
        int c8 = (idx & 7) * 8;
        int grow = rowbase + r;
        uint4 v = make_uint4(0u, 0u, 0u, 0u);
        if (grow < NN) {
            const uint4* src = half_sel ? (const uint4*)&g_lap16[grow * HH + c8]
                                        : (const uint4*)&g_h16[grow * HH + c8];
            v = __ldg(src);
        }
        __half* dst = half_sel ? &Ls[r * SW + c8] : &Hs[r * SW + c8];
        *(uint4*)dst = v;
    }
    __syncthreads();

    int warp = tid >> 5, lane = tid & 31;
    int R0 = warp * 16;
    uint32_t sb = (uint32_t)__cvta_generic_to_shared(dsm);

    float acc[8][4];
    int cq = 2 * (lane & 3);
#pragma unroll
    for (int q = 0; q < 8; q++) {
        float bb0 = __ldg(&b2[q * 8 + cq]);
        float bb1 = __ldg(&b2[q * 8 + cq + 1]);
        acc[q][0] = bb0; acc[q][1] = bb1; acc[q][2] = bb0; acc[q][3] = bb1;
    }

    int ar = R0 + (lane & 15);
    int ac = (lane >> 4) << 3;
    int br = ((lane >> 3) & 1) * 8 + (lane & 7);
    int bc = (lane >> 4) << 3;

#pragma unroll
    for (int ki = 0; ki < 4; ki++) {
        int k0 = ki * 16;
        uint32_t ha0, ha1, ha2, ha3, la0, la1, la2, la3;
        ldsm_x4(ha0, ha1, ha2, ha3, sb + OFF_H + (ar * SW + k0 + ac) * 2);
        ldsm_x4(la0, la1, la2, la3, sb + OFF_L + (ar * SW + k0 + ac) * 2);
#pragma unroll
        for (int p = 0; p < 4; p++) {
            int n0 = p * 16;
            uint32_t w0, w1, w2, w3;
            ldsm_x4_t(w0, w1, w2, w3, sb + OFF_W20 + ((k0 + br) * SW + n0 + bc) * 2);
            mma16816(acc[2 * p],     ha0, ha1, ha2, ha3, w0, w1);
            mma16816(acc[2 * p + 1], ha0, ha1, ha2, ha3, w2, w3);
            uint32_t v0, v1, v2, v3;
            ldsm_x4_t(v0, v1, v2, v3, sb + OFF_W21 + ((k0 + br) * SW + n0 + bc) * 2);
            mma16816(acc[2 * p],     la0, la1, la2, la3, v0, v1);
            mma16816(acc[2 * p + 1], la0, la1, la2, la3, v2, v3);
        }
    }

    // s = relu(acc) + h16  -> Ls (own rows only)
    int rr = lane >> 2;
#pragma unroll
    for (int q = 0; q < 8; q++) {
        int c = q * 8 + cq;
        float2 h0 = __half22float2(*(__half2*)&Hs[(R0 + rr) * SW + c]);
        float2 h1 = __half22float2(*(__half2*)&Hs[(R0 + rr + 8) * SW + c]);
        __half2 s0 = __floats2half2_rn(fmaxf(acc[q][0], 0.f) + h0.x,
                                       fmaxf(acc[q][1], 0.f) + h0.y);
        __half2 s1 = __floats2half2_rn(fmaxf(acc[q][2], 0.f) + h1.x,
                                       fmaxf(acc[q][3], 0.f) + h1.y);
        *(__half2*)&Ls[(R0 + rr) * SW + c] = s0;
        *(__half2*)&Ls[(R0 + rr + 8) * SW + c] = s1;
    }
    __syncthreads();

    // logits: pbuf[r][c] = s[r] . Wl[:,c] + bl[c]   (Wlf already resident)
    for (int o = tid; o < 128 * CC; o += 256) {
        int r = o / CC, c = o - r * CC;
        float a = __ldg(&bl[c]);
        const __half2* srow = (const __half2*)&Ls[r * SW];
#pragma unroll
        for (int k2 = 0; k2 < 32; k2++) {
            float2 f = __half22float2(srow[k2]);
            a = fmaf(f.x, Wlf[(2 * k2) * CC + c], a);
            a = fmaf(f.y, Wlf[(2 * k2 + 1) * CC + c], a);
        }
        pb[o] = a;
    }
    __syncthreads();

    if (tid < 128) {
        int row = rowbase + tid;
        if (row < NN) {
            float p[CC];
            float m = -1e30f;
#pragma unroll
            for (int c = 0; c < CC; c++) {
                p[c] = pb[tid * CC + c];
                m = fmaxf(m, p[c]);
            }
            float sum = 0.f;
#pragma unroll
            for (int c = 0; c < CC; c++) sum += expf(p[c] - m);
            float lse = logf(sum);
#pragma unroll
            for (int c = 0; c < CC; c++) out[row * CC + c] = p[c] - m - lse;
        }
    }

    // Tail: reset cnt/degi for next replay
    if (tid < 128) {
        int row = rowbase + tid;
        if (row < NN) g_cnt[row] = 0;
    }
    for (int i = blockIdx.x * 256 + tid; i < NN; i += gridDim.x * 256) g_degi[i] = 0;
}

// ---------------------------------------------------------------------------
extern "C" void kernel_launch(void* const* d_in, const int* in_sizes, int n_in,
                              void* d_out, int out_size) {
    const float* x   = (const float*)d_in[0];
    const int*   ei  = (const int*)d_in[1];
    const float* W1  = (const float*)d_in[2];
    const float* b1  = (const float*)d_in[3];
    const float* W20 = (const float*)d_in[4];
    const float* W21 = (const float*)d_in[5];
    const float* b2  = (const float*)d_in[6];
    const float* Wl  = (const float*)d_in[7];
    const float* bl  = (const float*)d_in[8];
    float* out = (float*)d_out;

    static cudaStream_t sB = 0;
    static cudaEvent_t e0 = 0, e1 = 0;
    static int init_done = 0;
    if (!init_done) {
        cudaFuncSetAttribute(k_final2, cudaFuncAttributeMaxDynamicSharedMemorySize, SMEM_F2);
        cudaStreamCreateWithFlags(&sB, cudaStreamNonBlocking);
        cudaEventCreateWithFlags(&e0, cudaEventDisableTiming);
        cudaEventCreateWithFlags(&e1, cudaEventDisableTiming);
        init_done = 1;
    }

    const int GB = (NN + 127) / 128;     // 391
    const int EB = (EE + 4095) / 4096;   // 196

    // Fork stream B for the graph-independent GEMM1
    cudaEventRecord(e0, 0);
    cudaStreamWaitEvent(sB, e0, 0);
    k_gemm1<<<GB, 512, 0, sB>>>(x, W1, b1);
    cudaEventRecord(e1, sB);

    // Stream A: fused hist+fill (single edge pass)
    k_fill<<<EB, 512>>>(ei);

    // Join: gather needs h16 (B) + buckets (A)
    cudaStreamWaitEvent(0, e1, 0);
    k_gather<<<(NN * 8 + 255) / 256, 256>>>();
    k_final2<<<GB, 256, SMEM_F2>>>(W20, W21, b2, Wl, bl, out);
}

// round 13
// speedup vs baseline: 1.2054x; 1.1707x over previous
#include <cuda_runtime.h>
#include <cuda_fp16.h>
#include <cstdint>

#define NN 50000
#define EE 800000
#define HH 64
#define CC 10
#define CAP 96   // bucket capacity per dst row (max in-degree ~42; 20+ sigma margin)

// Scratch (allocation-free: __device__ globals; zero-init at load, re-zeroed
// by the tail of k_final2 each replay)
__device__ int g_degi[NN];              // out-degree by src
__device__ int g_cnt[NN];               // in-degree by dst (bucket fill level)
__device__ int g_srcs[NN * CAP];        // bucketed src indices: row d at d*CAP
__device__ __align__(16) __half g_h16[NN * HH];   // fp16 h
__device__ __align__(16) __half g_lap16[NN * HH]; // fp16 lap

// ---------------------------------------------------------------------------
__device__ __forceinline__ int detect_stride(const int* __restrict__ p, int* s_st) {
    if (threadIdx.x < 32) {
        int bad = (p[2 * threadIdx.x + 1] != 0);
        unsigned b = __ballot_sync(0xffffffffu, bad);
        if (threadIdx.x == 0) *s_st = b ? 1 : 2;
    }
    __syncthreads();
    return *s_st;
}

// ---------------------------------------------------------------------------
// mma.sync helpers
// ---------------------------------------------------------------------------
__device__ __forceinline__ void ldsm_x4(uint32_t& r0, uint32_t& r1, uint32_t& r2,
                                        uint32_t& r3, uint32_t addr) {
    asm volatile("ldmatrix.sync.aligned.m8n8.x4.shared.b16 {%0,%1,%2,%3}, [%4];"
                 : "=r"(r0), "=r"(r1), "=r"(r2), "=r"(r3) : "r"(addr));
}
__device__ __forceinline__ void ldsm_x4_t(uint32_t& r0, uint32_t& r1, uint32_t& r2,
                                          uint32_t& r3, uint32_t addr) {
    asm volatile("ldmatrix.sync.aligned.m8n8.x4.trans.shared.b16 {%0,%1,%2,%3}, [%4];"
                 : "=r"(r0), "=r"(r1), "=r"(r2), "=r"(r3) : "r"(addr));
}
__device__ __forceinline__ void mma16816(float* c, uint32_t a0, uint32_t a1,
                                         uint32_t a2, uint32_t a3,
                                         uint32_t b0, uint32_t b1) {
    asm volatile(
        "mma.sync.aligned.m16n8k16.row.col.f32.f16.f16.f32 "
        "{%0,%1,%2,%3}, {%4,%5,%6,%7}, {%8,%9}, {%0,%1,%2,%3};"
        : "+f"(c[0]), "+f"(c[1]), "+f"(c[2]), "+f"(c[3])
        : "r"(a0), "r"(a1), "r"(a2), "r"(a3), "r"(b0), "r"(b1));
}

// ---------------------------------------------------------------------------
// A0: fused hist + bucket fill (single pass over edges). 4 edges/thread ILP
// (391 blocks — measured faster than ILP-8/196 blocks in R10 vs R12).
// ---------------------------------------------------------------------------
__global__ __launch_bounds__(512) void k_fill(const int* __restrict__ ei) {
    __shared__ int s_st;
    int st = detect_stride(ei, &s_st);
    int base = blockIdx.x * 2048 + threadIdx.x;
    int s[4], d[4], pos[4];
#pragma unroll
    for (int j = 0; j < 4; j++) {
        int e = base + j * 512;
        if (e < EE) {
            s[j] = __ldg(&ei[e * st]);
            d[j] = __ldg(&ei[(EE + e) * st]);
        } else { s[j] = -1; d[j] = 0; }
    }
#pragma unroll
    for (int j = 0; j < 4; j++)
        if (s[j] >= 0) pos[j] = atomicAdd(&g_cnt[d[j]], 1);
#pragma unroll
    for (int j = 0; j < 4; j++)
        if (s[j] >= 0) {
            if (pos[j] < CAP) g_srcs[d[j] * CAP + pos[j]] = s[j];
            atomicAdd(&g_degi[s[j]], 1);
        }
}

// ---------------------------------------------------------------------------
// B0 (concurrent stream): HMMA GEMM1  h16 = fp16(relu(x@W1+b1))
//   256 threads, 8 warps; 128 rows/block; warp = 16-row m-tile.
//   x,W1 converted to fp16 in smem; mma.m16n8k16 fp32 accum.
//   Each warp's A-frags read only its own 16 rows -> writeback into the
//   x smem rows needs no block sync; then coalesced uint4 copy to global.
// ---------------------------------------------------------------------------
#define G1_SW 72
#define G1_OFF_X 0
#define G1_OFF_W 18432
#define G1_SMEM 27648

__global__ __launch_bounds__(256) void k_gemm1(const float* __restrict__ x,
                                               const float* __restrict__ W1,
                                               const float* __restrict__ b1) {
    extern __shared__ char g1sm[];
    __half* Xs = (__half*)(g1sm + G1_OFF_X);   // [128][72]
    __half* Ws = (__half*)(g1sm + G1_OFF_W);   // [64][72]

    int tid = threadIdx.x;
    int rowbase = blockIdx.x * 128;

    // Load x tile (f32 -> fp16), 8 float4 per thread
#pragma unroll
    for (int j = 0; j < 8; j++) {
        int idx = j * 256 + tid;           // 0..2047 float4 index
        int r = idx >> 4;
        int kq = (idx & 15) << 2;
        int grow = rowbase + r;
        float4 v = make_float4(0.f, 0.f, 0.f, 0.f);
        if (grow < NN) v = *(const float4*)&x[grow * HH + kq];
        __half2 p0 = __floats2half2_rn(v.x, v.y);
        __half2 p1 = __floats2half2_rn(v.z, v.w);
        uint2 pk;
        pk.x = *(unsigned*)&p0;
        pk.y = *(unsigned*)&p1;
        *(uint2*)&Xs[r * G1_SW + kq] = pk;
    }
    // Load W1 (f32 -> fp16)
    for (int i = tid; i < HH * HH; i += 256) {
        int k = i >> 6, n = i & 63;
        Ws[k * G1_SW + n] = __float2half(W1[i]);
    }
    __syncthreads();

    int warp = tid >> 5, lane = tid & 31;
    int R0 = warp * 16;
    uint32_t sb = (uint32_t)__cvta_generic_to_shared(g1sm);

    float acc[8][4];
    int cq = 2 * (lane & 3);
    int rr = lane >> 2;
#pragma unroll
    for (int q = 0; q < 8; q++) {
        float bb0 = __ldg(&b1[q * 8 + cq]);
        float bb1 = __ldg(&b1[q * 8 + cq + 1]);
        acc[q][0] = bb0; acc[q][1] = bb1; acc[q][2] = bb0; acc[q][3] = bb1;
    }

    int ar = R0 + (lane & 15);
    int ac = (lane >> 4) << 3;
    int br = ((lane >> 3) & 1) * 8 + (lane & 7);
    int bc = (lane >> 4) << 3;

#pragma unroll
    for (int ki = 0; ki < 4; ki++) {
        int k0 = ki * 16;
        uint32_t a0, a1, a2, a3;
        ldsm_x4(a0, a1, a2, a3, sb + G1_OFF_X + (ar * G1_SW + k0 + ac) * 2);
#pragma unroll
        for (int p = 0; p < 4; p++) {
            int n0 = p * 16;
            uint32_t w0, w1, w2, w3;
            ldsm_x4_t(w0, w1, w2, w3, sb + G1_OFF_W + ((k0 + br) * G1_SW + n0 + bc) * 2);
            mma16816(acc[2 * p],     a0, a1, a2, a3, w0, w1);
            mma16816(acc[2 * p + 1], a0, a1, a2, a3, w2, w3);
        }
    }

    // relu + writeback into OWN warp's x rows (no block sync needed)
#pragma unroll
    for (int q = 0; q < 8; q++) {
        int c = q * 8 + cq;
        __half2 s0 = __floats2half2_rn(fmaxf(acc[q][0], 0.f), fmaxf(acc[q][1], 0.f));
        __half2 s1 = __floats2half2_rn(fmaxf(acc[q][2], 0.f), fmaxf(acc[q][3], 0.f));
        *(__half2*)&Xs[(R0 + rr) * G1_SW + c] = s0;
        *(__half2*)&Xs[(R0 + rr + 8) * G1_SW + c] = s1;
    }
    __syncwarp();

    // Coalesced copy of own warp's 16 rows to global (4 uint4 per lane)
#pragma unroll
    for (int j = 0; j < 4; j++) {
        int i = j * 32 + lane;             // 0..127 uint4 index within warp tile
        int rl = R0 + (i >> 3);
        int c8 = (i & 7) * 8;
        int grow = rowbase + rl;
        if (grow < NN)
            *(uint4*)&g_h16[grow * HH + c8] = *(uint4*)&Xs[rl * G1_SW + c8];
    }
}

// ---------------------------------------------------------------------------
// A1 (after join): bucket gather -> lap16
// ---------------------------------------------------------------------------
__global__ __launch_bounds__(256) void k_gather() {
    int gt = blockIdx.x * 256 + threadIdx.x;
    int row = gt >> 3;
    int l = gt & 7;
    if (row >= NN) return;
    unsigned gmask = 0xffu << (threadIdx.x & 24);  // own 8-lane group

    int len = min(__ldg(&g_cnt[row]), CAP);
    int start = row * CAP;

    float a0 = 0.f, a1 = 0.f, a2 = 0.f, a3 = 0.f;
    float a4 = 0.f, a5 = 0.f, a6 = 0.f, a7 = 0.f;

    for (int base = 0; base < len; base += 8) {
        int j = base + l;
        int s = 0;
        float w = 0.f;
        if (j < len) {
            s = __ldg(&g_srcs[start + j]);
            int dg = __ldg(&g_degi[s]);
            w = (dg > 0) ? rsqrtf((float)dg) : 0.f;
        }
        int m = min(8, len - base);
#pragma unroll 4
        for (int jj = 0; jj < m; jj++) {
            int sj = __shfl_sync(gmask, s, jj, 8);
            float wj = __shfl_sync(gmask, w, jj, 8);
            uint4 u = __ldg((const uint4*)&g_h16[sj * HH + l * 8]);
            float2 f0 = __half22float2(*(__half2*)&u.x);
            float2 f1 = __half22float2(*(__half2*)&u.y);
            float2 f2 = __half22float2(*(__half2*)&u.z);
            float2 f3 = __half22float2(*(__half2*)&u.w);
            a0 = fmaf(wj, f0.x, a0); a1 = fmaf(wj, f0.y, a1);
            a2 = fmaf(wj, f1.x, a2); a3 = fmaf(wj, f1.y, a3);
            a4 = fmaf(wj, f2.x, a4); a5 = fmaf(wj, f2.y, a5);
            a6 = fmaf(wj, f3.x, a6); a7 = fmaf(wj, f3.y, a7);
        }
    }
    int dgr = __ldg(&g_degi[row]);
    float sc = (dgr > 0) ? -rsqrtf((float)dgr) : 0.f;
    __half2 o0 = __floats2half2_rn(a0 * sc, a1 * sc);
    __half2 o1 = __floats2half2_rn(a2 * sc, a3 * sc);
    __half2 o2 = __floats2half2_rn(a4 * sc, a5 * sc);
    __half2 o3 = __floats2half2_rn(a6 * sc, a7 * sc);
    uint4 ov;
    ov.x = *(unsigned*)&o0; ov.y = *(unsigned*)&o1;
    ov.z = *(unsigned*)&o2; ov.w = *(unsigned*)&o3;
    *(uint4*)&g_lap16[row * HH + l * 8] = ov;
}

// ---------------------------------------------------------------------------
// A2: tensor-core dual GEMM + smem epilogue (R12 layout, proven 22.2 us).
// ---------------------------------------------------------------------------
#define SW 72
#define OFF_H 0
#define OFF_L 18432
#define OFF_W20 36864
#define OFF_W21 46080
#define OFF_WL 55296            // Wl fp32 [64][10] = 2560 B
#define OFF_PB 57856            // pbuf fp32 [128][10] = 5120 B
#define SMEM_F2 62976

__global__ __launch_bounds__(256) void k_final2(const float* __restrict__ W20,
                                                const float* __restrict__ W21,
                                                const float* __restrict__ b2,
                                                const float* __restrict__ Wl,
                                                const float* __restrict__ bl,
                                                float* __restrict__ out) {
    extern __shared__ char dsm[];
    __half* Hs = (__half*)(dsm + OFF_H);
    __half* Ls = (__half*)(dsm + OFF_L);
    __half* W20s = (__half*)(dsm + OFF_W20);
    __half* W21s = (__half*)(dsm + OFF_W21);
    float* Wlf = (float*)(dsm + OFF_WL);
    float* pb  = (float*)(dsm + OFF_PB);

    int tid = threadIdx.x;
    int rowbase = blockIdx.x * 128;

    for (int i = tid; i < HH * HH; i += 256) {
        int k = i >> 6, n = i & 63;
        W20s[k * SW + n] = __float2half(W20[i]);
        W21s[k * SW + n] = __float2half(W21[i]);
    }
    for (int i = tid; i < HH * CC; i += 256) Wlf[i] = __ldg(&Wl[i]);
#pragma unroll
    for (int j = 0; j < 8; j++) {
        int idx = j * 256 + tid;           // 0..2047
        int half_sel = idx >> 10;          // 0: h, 1: lap
        int r = (idx >> 3) & 127;
        int c8 = (idx & 7) * 8;
        int grow = rowbase + r;
        uint4 v = make_uint4(0u, 0u, 0u, 0u);
        if (grow < NN) {
            const uint4* src = half_sel ? (const uint4*)&g_lap16[grow * HH + c8]
                                        : (const uint4*)&g_h16[grow * HH + c8];
            v = __ldg(src);
        }
        __half* dst = half_sel ? &Ls[r * SW + c8] : &Hs[r * SW + c8];
        *(uint4*)dst = v;
    }
    __syncthreads();

    int warp = tid >> 5, lane = tid & 31;
    int R0 = warp * 16;
    uint32_t sb = (uint32_t)__cvta_generic_to_shared(dsm);

    float acc[8][4];
    int cq = 2 * (lane & 3);
#pragma unroll
    for (int q = 0; q < 8; q++) {
        float bb0 = __ldg(&b2[q * 8 + cq]);
        float bb1 = __ldg(&b2[q * 8 + cq + 1]);
        acc[q][0] = bb0; acc[q][1] = bb1; acc[q][2] = bb0; acc[q][3] = bb1;
    }

    int ar = R0 + (lane & 15);
    int ac = (lane >> 4) << 3;
    int br = ((lane >> 3) & 1) * 8 + (lane & 7);
    int bc = (lane >> 4) << 3;

#pragma unroll
    for (int ki = 0; ki < 4; ki++) {
        int k0 = ki * 16;
        uint32_t ha0, ha1, ha2, ha3, la0, la1, la2, la3;
        ldsm_x4(ha0, ha1, ha2, ha3, sb + OFF_H + (ar * SW + k0 + ac) * 2);
        ldsm_x4(la0, la1, la2, la3, sb + OFF_L + (ar * SW + k0 + ac) * 2);
#pragma unroll
        for (int p = 0; p < 4; p++) {
            int n0 = p * 16;
            uint32_t w0, w1, w2, w3;
            ldsm_x4_t(w0, w1, w2, w3, sb + OFF_W20 + ((k0 + br) * SW + n0 + bc) * 2);
            mma16816(acc[2 * p],     ha0, ha1, ha2, ha3, w0, w1);
            mma16816(acc[2 * p + 1], ha0, ha1, ha2, ha3, w2, w3);
            uint32_t v0, v1, v2, v3;
            ldsm_x4_t(v0, v1, v2, v3, sb + OFF_W21 + ((k0 + br) * SW + n0 + bc) * 2);
            mma16816(acc[2 * p],     la0, la1, la2, la3, v0, v1);
            mma16816(acc[2 * p + 1], la0, la1, la2, la3, v2, v3);
        }
    }

    // s = relu(acc) + h16  -> Ls (own rows only)
    int rr = lane >> 2;
#pragma unroll
    for (int q = 0; q < 8; q++) {
        int c = q * 8 + cq;
        float2 h0 = __half22float2(*(__half2*)&Hs[(R0 + rr) * SW + c]);
        float2 h1 = __half22float2(*(__half2*)&Hs[(R0 + rr + 8) * SW + c]);
        __half2 s0 = __floats2half2_rn(fmaxf(acc[q][0], 0.f) + h0.x,
                                       fmaxf(acc[q][1], 0.f) + h0.y);
        __half2 s1 = __floats2half2_rn(fmaxf(acc[q][2], 0.f) + h1.x,
                                       fmaxf(acc[q][3], 0.f) + h1.y);
        *(__half2*)&Ls[(R0 + rr) * SW + c] = s0;
        *(__half2*)&Ls[(R0 + rr + 8) * SW + c] = s1;
    }
    __syncthreads();

    // logits: pbuf[r][c] = s[r] . Wl[:,c] + bl[c]
    for (int o = tid; o < 128 * CC; o += 256) {
        int r = o / CC, c = o - r * CC;
        float a = __ldg(&bl[c]);
        const __half2* srow = (const __half2*)&Ls[r * SW];
#pragma unroll
        for (int k2 = 0; k2 < 32; k2++) {
            float2 f = __half22float2(srow[k2]);
            a = fmaf(f.x, Wlf[(2 * k2) * CC + c], a);
            a = fmaf(f.y, Wlf[(2 * k2 + 1) * CC + c], a);
        }
        pb[o] = a;
    }
    __syncthreads();

    if (tid < 128) {
        int row = rowbase + tid;
        if (row < NN) {
            float p[CC];
            float m = -1e30f;
#pragma unroll
            for (int c = 0; c < CC; c++) {
                p[c] = pb[tid * CC + c];
                m = fmaxf(m, p[c]);
            }
            float sum = 0.f;
#pragma unroll
            for (int c = 0; c < CC; c++) sum += expf(p[c] - m);
            float lse = logf(sum);
#pragma unroll
            for (int c = 0; c < CC; c++) out[row * CC + c] = p[c] - m - lse;
        }
    }

    // Tail: reset cnt/degi for next replay
    if (tid < 128) {
        int row = rowbase + tid;
        if (row < NN) g_cnt[row] = 0;
    }
    for (int i = blockIdx.x * 256 + tid; i < NN; i += gridDim.x * 256) g_degi[i] = 0;
}

// ---------------------------------------------------------------------------
extern "C" void kernel_launch(void* const* d_in, const int* in_sizes, int n_in,
                              void* d_out, int out_size) {
    const float* x   = (const float*)d_in[0];
    const int*   ei  = (const int*)d_in[1];
    const float* W1  = (const float*)d_in[2];
    const float* b1  = (const float*)d_in[3];
    const float* W20 = (const float*)d_in[4];
    const float* W21 = (const float*)d_in[5];
    const float* b2  = (const float*)d_in[6];
    const float* Wl  = (const float*)d_in[7];
    const float* bl  = (const float*)d_in[8];
    float* out = (float*)d_out;

    static cudaStream_t sB = 0;
    static cudaEvent_t e0 = 0, e1 = 0;
    static int init_done = 0;
    if (!init_done) {
        cudaFuncSetAttribute(k_final2, cudaFuncAttributeMaxDynamicSharedMemorySize, SMEM_F2);
        cudaFuncSetAttribute(k_gemm1, cudaFuncAttributeMaxDynamicSharedMemorySize, G1_SMEM);
        cudaStreamCreateWithFlags(&sB, cudaStreamNonBlocking);
        cudaEventCreateWithFlags(&e0, cudaEventDisableTiming);
        cudaEventCreateWithFlags(&e1, cudaEventDisableTiming);
        init_done = 1;
    }

    const int GB = (NN + 127) / 128;     // 391
    const int EB = (EE + 2047) / 2048;   // 391

    // Fork stream B for the graph-independent GEMM1
    cudaEventRecord(e0, 0);
    cudaStreamWaitEvent(sB, e0, 0);
    k_gemm1<<<GB, 256, G1_SMEM, sB>>>(x, W1, b1);
    cudaEventRecord(e1, sB);

    // Stream A: fused hist+fill (single edge pass)
    k_fill<<<EB, 512>>>(ei);

    // Join: gather needs h16 (B) + buckets (A)
    cudaStreamWaitEvent(0, e1, 0);
    k_gather<<<(NN * 8 + 255) / 256, 256>>>();
    k_final2<<<GB, 256, SMEM_F2>>>(W20, W21, b2, Wl, bl, out);
}

// round 14
// speedup vs baseline: 1.2577x; 1.0434x over previous
#include <cuda_runtime.h>
#include <cuda_fp16.h>
#include <cstdint>

#define NN 50000
#define EE 800000
#define HH 64
#define CC 10
#define CAP 96   // bucket capacity per dst row (max in-degree ~42; 20+ sigma margin)

// Scratch (allocation-free: __device__ globals; zero-init at load, re-zeroed
// by the tail of k_final2 each replay)
__device__ int g_degi[NN];              // out-degree by src
__device__ int g_cnt[NN];               // in-degree by dst (bucket fill level)
__device__ int g_srcs[NN * CAP];        // bucketed src indices: row d at d*CAP
__device__ __align__(16) __half g_h16[NN * HH];   // fp16 h
__device__ __align__(16) __half g_lap16[NN * HH]; // fp16 lap

// ---------------------------------------------------------------------------
__device__ __forceinline__ int detect_stride(const int* __restrict__ p, int* s_st) {
    if (threadIdx.x < 32) {
        int bad = (p[2 * threadIdx.x + 1] != 0);
        unsigned b = __ballot_sync(0xffffffffu, bad);
        if (threadIdx.x == 0) *s_st = b ? 1 : 2;
    }
    __syncthreads();
    return *s_st;
}

// ---------------------------------------------------------------------------
// mma.sync helpers
// ---------------------------------------------------------------------------
__device__ __forceinline__ void ldsm_x4(uint32_t& r0, uint32_t& r1, uint32_t& r2,
                                        uint32_t& r3, uint32_t addr) {
    asm volatile("ldmatrix.sync.aligned.m8n8.x4.shared.b16 {%0,%1,%2,%3}, [%4];"
                 : "=r"(r0), "=r"(r1), "=r"(r2), "=r"(r3) : "r"(addr));
}
__device__ __forceinline__ void ldsm_x4_t(uint32_t& r0, uint32_t& r1, uint32_t& r2,
                                          uint32_t& r3, uint32_t addr) {
    asm volatile("ldmatrix.sync.aligned.m8n8.x4.trans.shared.b16 {%0,%1,%2,%3}, [%4];"
                 : "=r"(r0), "=r"(r1), "=r"(r2), "=r"(r3) : "r"(addr));
}
__device__ __forceinline__ void mma16816(float* c, uint32_t a0, uint32_t a1,
                                         uint32_t a2, uint32_t a3,
                                         uint32_t b0, uint32_t b1) {
    asm volatile(
        "mma.sync.aligned.m16n8k16.row.col.f32.f16.f16.f32 "
        "{%0,%1,%2,%3}, {%4,%5,%6,%7}, {%8,%9}, {%0,%1,%2,%3};"
        : "+f"(c[0]), "+f"(c[1]), "+f"(c[2]), "+f"(c[3])
        : "r"(a0), "r"(a1), "r"(a2), "r"(a3), "r"(b0), "r"(b1));
}

// ---------------------------------------------------------------------------
// A0: fused hist + bucket fill (single pass over edges). 4 edges/thread ILP.
// ---------------------------------------------------------------------------
__global__ __launch_bounds__(512) void k_fill(const int* __restrict__ ei) {
    __shared__ int s_st;
    int st = detect_stride(ei, &s_st);
    int base = blockIdx.x * 2048 + threadIdx.x;
    int s[4], d[4], pos[4];
#pragma unroll
    for (int j = 0; j < 4; j++) {
        int e = base + j * 512;
        if (e < EE) {
            s[j] = __ldg(&ei[e * st]);
            d[j] = __ldg(&ei[(EE + e) * st]);
        } else { s[j] = -1; d[j] = 0; }
    }
#pragma unroll
    for (int j = 0; j < 4; j++)
        if (s[j] >= 0) pos[j] = atomicAdd(&g_cnt[d[j]], 1);
#pragma unroll
    for (int j = 0; j < 4; j++)
        if (s[j] >= 0) {
            if (pos[j] < CAP) g_srcs[d[j] * CAP + pos[j]] = s[j];
            atomicAdd(&g_degi[s[j]], 1);
        }
}

// ---------------------------------------------------------------------------
// B0 (concurrent stream): HMMA GEMM1  h16 = fp16(relu(x@W1+b1))
// ---------------------------------------------------------------------------
#define G1_SW 72
#define G1_OFF_X 0
#define G1_OFF_W 18432
#define G1_SMEM 27648

__global__ __launch_bounds__(256) void k_gemm1(const float* __restrict__ x,
                                               const float* __restrict__ W1,
                                               const float* __restrict__ b1) {
    extern __shared__ char g1sm[];
    __half* Xs = (__half*)(g1sm + G1_OFF_X);   // [128][72]
    __half* Ws = (__half*)(g1sm + G1_OFF_W);   // [64][72]

    int tid = threadIdx.x;
    int rowbase = blockIdx.x * 128;

#pragma unroll
    for (int j = 0; j < 8; j++) {
        int idx = j * 256 + tid;           // 0..2047 float4 index
        int r = idx >> 4;
        int kq = (idx & 15) << 2;
        int grow = rowbase + r;
        float4 v = make_float4(0.f, 0.f, 0.f, 0.f);
        if (grow < NN) v = *(const float4*)&x[grow * HH + kq];
        __half2 p0 = __floats2half2_rn(v.x, v.y);
        __half2 p1 = __floats2half2_rn(v.z, v.w);
        uint2 pk;
        pk.x = *(unsigned*)&p0;
        pk.y = *(unsigned*)&p1;
        *(uint2*)&Xs[r * G1_SW + kq] = pk;
    }
    for (int i = tid; i < HH * HH; i += 256) {
        int k = i >> 6, n = i & 63;
        Ws[k * G1_SW + n] = __float2half(W1[i]);
    }
    __syncthreads();

    int warp = tid >> 5, lane = tid & 31;
    int R0 = warp * 16;
    uint32_t sb = (uint32_t)__cvta_generic_to_shared(g1sm);

    float acc[8][4];
    int cq = 2 * (lane & 3);
    int rr = lane >> 2;
#pragma unroll
    for (int q = 0; q < 8; q++) {
        float bb0 = __ldg(&b1[q * 8 + cq]);
        float bb1 = __ldg(&b1[q * 8 + cq + 1]);
        acc[q][0] = bb0; acc[q][1] = bb1; acc[q][2] = bb0; acc[q][3] = bb1;
    }

    int ar = R0 + (lane & 15);
    int ac = (lane >> 4) << 3;
    int br = ((lane >> 3) & 1) * 8 + (lane & 7);
    int bc = (lane >> 4) << 3;

#pragma unroll
    for (int ki = 0; ki < 4; ki++) {
        int k0 = ki * 16;
        uint32_t a0, a1, a2, a3;
        ldsm_x4(a0, a1, a2, a3, sb + G1_OFF_X + (ar * G1_SW + k0 + ac) * 2);
#pragma unroll
        for (int p = 0; p < 4; p++) {
            int n0 = p * 16;
            uint32_t w0, w1, w2, w3;
            ldsm_x4_t(w0, w1, w2, w3, sb + G1_OFF_W + ((k0 + br) * G1_SW + n0 + bc) * 2);
            mma16816(acc[2 * p],     a0, a1, a2, a3, w0, w1);
            mma16816(acc[2 * p + 1], a0, a1, a2, a3, w2, w3);
        }
    }

    // relu + writeback into OWN warp's x rows (no block sync needed)
#pragma unroll
    for (int q = 0; q < 8; q++) {
        int c = q * 8 + cq;
        __half2 s0 = __floats2half2_rn(fmaxf(acc[q][0], 0.f), fmaxf(acc[q][1], 0.f));
        __half2 s1 = __floats2half2_rn(fmaxf(acc[q][2], 0.f), fmaxf(acc[q][3], 0.f));
        *(__half2*)&Xs[(R0 + rr) * G1_SW + c] = s0;
        *(__half2*)&Xs[(R0 + rr + 8) * G1_SW + c] = s1;
    }
    __syncwarp();

#pragma unroll
    for (int j = 0; j < 4; j++) {
        int i = j * 32 + lane;             // 0..127 uint4 index within warp tile
        int rl = R0 + (i >> 3);
        int c8 = (i & 7) * 8;
        int grow = rowbase + rl;
        if (grow < NN)
            *(uint4*)&g_h16[grow * HH + c8] = *(uint4*)&Xs[rl * G1_SW + c8];
    }
}

// ---------------------------------------------------------------------------
// A1 (after join): bucket gather -> lap16
// ---------------------------------------------------------------------------
__global__ __launch_bounds__(256) void k_gather() {
    int gt = blockIdx.x * 256 + threadIdx.x;
    int row = gt >> 3;
    int l = gt & 7;
    if (row >= NN) return;
    unsigned gmask = 0xffu << (threadIdx.x & 24);  // own 8-lane group

    int len = min(__ldg(&g_cnt[row]), CAP);
    int start = row * CAP;

    float a0 = 0.f, a1 = 0.f, a2 = 0.f, a3 = 0.f;
    float a4 = 0.f, a5 = 0.f, a6 = 0.f, a7 = 0.f;

    for (int base = 0; base < len; base += 8) {
        int j = base + l;
        int s = 0;
        float w = 0.f;
        if (j < len) {
            s = __ldg(&g_srcs[start + j]);
            int dg = __ldg(&g_degi[s]);
            w = (dg > 0) ? rsqrtf((float)dg) : 0.f;
        }
        int m = min(8, len - base);
#pragma unroll 4
        for (int jj = 0; jj < m; jj++) {
            int sj = __shfl_sync(gmask, s, jj, 8);
            float wj = __shfl_sync(gmask, w, jj, 8);
            uint4 u = __ldg((const uint4*)&g_h16[sj * HH + l * 8]);
            float2 f0 = __half22float2(*(__half2*)&u.x);
            float2 f1 = __half22float2(*(__half2*)&u.y);
            float2 f2 = __half22float2(*(__half2*)&u.z);
            float2 f3 = __half22float2(*(__half2*)&u.w);
            a0 = fmaf(wj, f0.x, a0); a1 = fmaf(wj, f0.y, a1);
            a2 = fmaf(wj, f1.x, a2); a3 = fmaf(wj, f1.y, a3);
            a4 = fmaf(wj, f2.x, a4); a5 = fmaf(wj, f2.y, a5);
            a6 = fmaf(wj, f3.x, a6); a7 = fmaf(wj, f3.y, a7);
        }
    }
    int dgr = __ldg(&g_degi[row]);
    float sc = (dgr > 0) ? -rsqrtf((float)dgr) : 0.f;
    __half2 o0 = __floats2half2_rn(a0 * sc, a1 * sc);
    __half2 o1 = __floats2half2_rn(a2 * sc, a3 * sc);
    __half2 o2 = __floats2half2_rn(a4 * sc, a5 * sc);
    __half2 o3 = __floats2half2_rn(a6 * sc, a7 * sc);
    uint4 ov;
    ov.x = *(unsigned*)&o0; ov.y = *(unsigned*)&o1;
    ov.z = *(unsigned*)&o2; ov.w = *(unsigned*)&o3;
    *(uint4*)&g_lap16[row * HH + l * 8] = ov;
}

// ---------------------------------------------------------------------------
// A2: tensor-core dual GEMM + tensor-core logits + quad-shuffle softmax.
//   acc = h16@W20 + lap16@W21 + b2  (mma, fp32 accum)
//   s = relu(acc)+h16 -> Ls (own warp rows only)
//   logits = s @ Wlp (fp16, padded 64x16) via 2nd MMA pass -> registers
//   log_softmax via quad shfl reduce; lanes write own columns.
//   ONE __syncthreads total. Tail: reset cnt/degi.
// ---------------------------------------------------------------------------
#define SW 72
#define WLS 24
#define OFF_H 0
#define OFF_L 18432
#define OFF_W20 36864
#define OFF_W21 46080
#define OFF_WLP 55296           // Wl fp16 [64][24] = 3072 B (cols 10-15 zero)
#define SMEM_F2 58368

__global__ __launch_bounds__(256) void k_final2(const float* __restrict__ W20,
                                                const float* __restrict__ W21,
                                                const float* __restrict__ b2,
                                                const float* __restrict__ Wl,
                                                const float* __restrict__ bl,
                                                float* __restrict__ out) {
    extern __shared__ char dsm[];
    __half* Hs = (__half*)(dsm + OFF_H);
    __half* Ls = (__half*)(dsm + OFF_L);
    __half* W20s = (__half*)(dsm + OFF_W20);
    __half* W21s = (__half*)(dsm + OFF_W21);
    __half* Wlp = (__half*)(dsm + OFF_WLP);

    int tid = threadIdx.x;
    int rowbase = blockIdx.x * 128;

    // Load weights (f32 -> fp16 smem)
    for (int i = tid; i < HH * HH; i += 256) {
        int k = i >> 6, n = i & 63;
        W20s[k * SW + n] = __float2half(W20[i]);
        W21s[k * SW + n] = __float2half(W21[i]);
    }
    for (int i = tid; i < HH * 16; i += 256) {
        int k = i >> 4, c = i & 15;
        Wlp[k * WLS + c] = (c < CC) ? __float2half(__ldg(&Wl[k * CC + c]))
                                    : __float2half(0.f);
    }
    // Load h16/lap16 tiles (uint4 = 8 halves)
#pragma unroll
    for (int j = 0; j < 8; j++) {
        int idx = j * 256 + tid;           // 0..2047
        int half_sel = idx >> 10;          // 0: h, 1: lap
        int r = (idx >> 3) & 127;
        int c8 = (idx & 7) * 8;
        int grow = rowbase + r;
        uint4 v = make_uint4(0u, 0u, 0u, 0u);
        if (grow < NN) {
            const uint4* src = half_sel ? (const uint4*)&g_lap16[grow * HH + c8]
                                        : (const uint4*)&g_h16[grow * HH + c8];
            v = __ldg(src);
        }
        __half* dst = half_sel ? &Ls[r * SW + c8] : &Hs[r * SW + c8];
        *(uint4*)dst = v;
    }
    __syncthreads();

    int warp = tid >> 5, lane = tid & 31;
    int R0 = warp * 16;
    uint32_t sb = (uint32_t)__cvta_generic_to_shared(dsm);

    float acc[8][4];
    int cq = 2 * (lane & 3);
    int rr = lane >> 2;
#pragma unroll
    for (int q = 0; q < 8; q++) {
        float bb0 = __ldg(&b2[q * 8 + cq]);
        float bb1 = __ldg(&b2[q * 8 + cq + 1]);
        acc[q][0] = bb0; acc[q][1] = bb1; acc[q][2] = bb0; acc[q][3] = bb1;
    }

    int ar = R0 + (lane & 15);
    int ac = (lane >> 4) << 3;
    int br = ((lane >> 3) & 1) * 8 + (lane & 7);
    int bc = (lane >> 4) << 3;

#pragma unroll
    for (int ki = 0; ki < 4; ki++) {
        int k0 = ki * 16;
        uint32_t ha0, ha1, ha2, ha3, la0, la1, la2, la3;
        ldsm_x4(ha0, ha1, ha2, ha3, sb + OFF_H + (ar * SW + k0 + ac) * 2);
        ldsm_x4(la0, la1, la2, la3, sb + OFF_L + (ar * SW + k0 + ac) * 2);
#pragma unroll
        for (int p = 0; p < 4; p++) {
            int n0 = p * 16;
            uint32_t w0, w1, w2, w3;
            ldsm_x4_t(w0, w1, w2, w3, sb + OFF_W20 + ((k0 + br) * SW + n0 + bc) * 2);
            mma16816(acc[2 * p],     ha0, ha1, ha2, ha3, w0, w1);
            mma16816(acc[2 * p + 1], ha0, ha1, ha2, ha3, w2, w3);
            uint32_t v0, v1, v2, v3;
            ldsm_x4_t(v0, v1, v2, v3, sb + OFF_W21 + ((k0 + br) * SW + n0 + bc) * 2);
            mma16816(acc[2 * p],     la0, la1, la2, la3, v0, v1);
            mma16816(acc[2 * p + 1], la0, la1, la2, la3, v2, v3);
        }
    }

    // s = relu(acc) + h16 -> Ls (own warp rows only)
#pragma unroll
    for (int q = 0; q < 8; q++) {
        int c = q * 8 + cq;
        float2 h0 = __half22float2(*(__half2*)&Hs[(R0 + rr) * SW + c]);
        float2 h1 = __half22float2(*(__half2*)&Hs[(R0 + rr + 8) * SW + c]);
        __half2 s0 = __floats2half2_rn(fmaxf(acc[q][0], 0.f) + h0.x,
                                       fmaxf(acc[q][1], 0.f) + h0.y);
        __half2 s1 = __floats2half2_rn(fmaxf(acc[q][2], 0.f) + h1.x,
                                       fmaxf(acc[q][3], 0.f) + h1.y);
        *(__half2*)&Ls[(R0 + rr) * SW + c] = s0;
        *(__half2*)&Ls[(R0 + rr + 8) * SW + c] = s1;
    }
    __syncwarp();   // own rows only: warp-local ordering suffices

    // Logits MMA: acc2 = s @ Wlp  (n-tile = 16, cols 0..15; 10 valid)
    float acc2[2][4];
#pragma unroll
    for (int p = 0; p < 2; p++) {
        acc2[p][0] = 0.f; acc2[p][1] = 0.f; acc2[p][2] = 0.f; acc2[p][3] = 0.f;
    }
#pragma unroll
    for (int ki = 0; ki < 4; ki++) {
        int k0 = ki * 16;
        uint32_t sa0, sa1, sa2, sa3;
        ldsm_x4(sa0, sa1, sa2, sa3, sb + OFF_L + (ar * SW + k0 + ac) * 2);
        uint32_t u0, u1, u2, u3;
        ldsm_x4_t(u0, u1, u2, u3, sb + OFF_WLP + ((k0 + br) * WLS + bc) * 2);
        mma16816(acc2[0], sa0, sa1, sa2, sa3, u0, u1);
        mma16816(acc2[1], sa0, sa1, sa2, sa3, u2, u3);
    }

    // Softmax: lane holds cols {cq, cq+1} (acc2[0]) and {cq+8, cq+9} (acc2[1])
    float bl0 = __ldg(&bl[cq]);
    float bl1 = __ldg(&bl[cq + 1]);
    float bl8 = (cq == 0) ? __ldg(&bl[8]) : 0.f;
    float bl9 = (cq == 0) ? __ldg(&bl[9]) : 0.f;
#pragma unroll
    for (int hsel = 0; hsel < 2; hsel++) {
        float v0 = acc2[0][2 * hsel]     + bl0;
        float v1 = acc2[0][2 * hsel + 1] + bl1;
        float v2 = (cq == 0) ? acc2[1][2 * hsel]     + bl8 : -1e30f;
        float v3 = (cq == 0) ? acc2[1][2 * hsel + 1] + bl9 : -1e30f;

        float m = fmaxf(fmaxf(v0, v1), fmaxf(v2, v3));
        m = fmaxf(m, __shfl_xor_sync(0xffffffffu, m, 1));
        m = fmaxf(m, __shfl_xor_sync(0xffffffffu, m, 2));

        float sum = expf(v0 - m) + expf(v1 - m);
        if (cq == 0) sum += expf(v2 - m) + expf(v3 - m);
        sum += __shfl_xor_sync(0xffffffffu, sum, 1);
        sum += __shfl_xor_sync(0xffffffffu, sum, 2);
        float lse = m + logf(sum);

        int row = rowbase + R0 + rr + hsel * 8;
        if (row < NN) {
            out[row * CC + cq]     = v0 - lse;
            out[row * CC + cq + 1] = v1 - lse;
            if (cq == 0) {
                out[row * CC + 8] = v2 - lse;
                out[row * CC + 9] = v3 - lse;
            }
        }
    }

    // Tail: reset cnt/degi for next replay
    if (tid < 128) {
        int row = rowbase + tid;
        if (row < NN) g_cnt[row] = 0;
    }
    for (int i = blockIdx.x * 256 + tid; i < NN; i += gridDim.x * 256) g_degi[i] = 0;
}

// ---------------------------------------------------------------------------
extern "C" void kernel_launch(void* const* d_in, const int* in_sizes, int n_in,
                              void* d_out, int out_size) {
    const float* x   = (const float*)d_in[0];
    const int*   ei  = (const int*)d_in[1];
    const float* W1  = (const float*)d_in[2];
    const float* b1  = (const float*)d_in[3];
    const float* W20 = (const float*)d_in[4];
    const float* W21 = (const float*)d_in[5];
    const float* b2  = (const float*)d_in[6];
    const float* Wl  = (const float*)d_in[7];
    const float* bl  = (const float*)d_in[8];
    float* out = (float*)d_out;

    static cudaStream_t sB = 0;
    static cudaEvent_t e0 = 0, e1 = 0;
    static int init_done = 0;
    if (!init_done) {
        cudaFuncSetAttribute(k_final2, cudaFuncAttributeMaxDynamicSharedMemorySize, SMEM_F2);
        cudaFuncSetAttribute(k_gemm1, cudaFuncAttributeMaxDynamicSharedMemorySize, G1_SMEM);
        cudaStreamCreateWithFlags(&sB, cudaStreamNonBlocking);
        cudaEventCreateWithFlags(&e0, cudaEventDisableTiming);
        cudaEventCreateWithFlags(&e1, cudaEventDisableTiming);
        init_done = 1;
    }

    const int GB = (NN + 127) / 128;     // 391
    const int EB = (EE + 2047) / 2048;   // 391

    // Fork stream B for the graph-independent GEMM1
    cudaEventRecord(e0, 0);
    cudaStreamWaitEvent(sB, e0, 0);
    k_gemm1<<<GB, 256, G1_SMEM, sB>>>(x, W1, b1);
    cudaEventRecord(e1, sB);

    // Stream A: fused hist+fill (single edge pass)
    k_fill<<<EB, 512>>>(ei);

    // Join: gather needs h16 (B) + buckets (A)
    cudaStreamWaitEvent(0, e1, 0);
    k_gather<<<(NN * 8 + 255) / 256, 256>>>();
    k_final2<<<GB, 256, SMEM_F2>>>(W20, W21, b2, Wl, bl, out);
}